// round 9
// baseline (speedup 1.0000x reference)
#include <cuda_runtime.h>
#include <cuda_fp16.h>
#include <cstdint>

#define NAB       128
#define NG        50
#define TBN       4096             // table intervals over [0, CUTOFF]
#define MAX_ATOMS 50000

typedef unsigned long long ull;

__device__ __align__(16) __half g_rf16[(size_t)MAX_ATOMS * NAB];     // 12.8 MB
__device__ __align__(16) float  g_agg[(size_t)MAX_ATOMS * NAB];      // 25.6 MB
__device__ __align__(16) __half g_tab16[(size_t)(TBN + 1) * NAB];    // 1 MB

__device__ __forceinline__ float sspf(float x) {
    return fmaxf(x, 0.0f) + log1pf(__expf(-fabsf(x))) - 0.6931471805599453f;
}

// ---- packed f32x2 helpers (sm_100+) ---------------------------------------
__device__ __forceinline__ ull pk2(float lo, float hi) {
    ull r; asm("mov.b64 %0, {%1, %2};" : "=l"(r) : "f"(lo), "f"(hi)); return r;
}
__device__ __forceinline__ ull fma2(ull a, ull b, ull c) {
    ull d; asm("fma.rn.f32x2 %0, %1, %2, %3;" : "=l"(d) : "l"(a), "l"(b), "l"(c));
    return d;
}
__device__ __forceinline__ float2 up2(ull v) {
    float2 f; asm("mov.b64 {%0, %1}, %2;" : "=f"(f.x), "=f"(f.y) : "l"(v));
    return f;
}

// ---------------------------------------------------------------------------
// rf = r @ W_af (stored fp16).  8 rows/warp, f32x2 FMA.
// ---------------------------------------------------------------------------
__global__ void __launch_bounds__(128) k_rf(const float* __restrict__ r,
                                            const float* __restrict__ Waf,
                                            int Nrows) {
    __shared__ __align__(16) float s_row[4][8][NAB];
    int w = threadIdx.x >> 5, l = threadIdx.x & 31;
    int f4 = l * 4;
    const float4 z4 = make_float4(0.f, 0.f, 0.f, 0.f);
    int noct = (Nrows + 7) >> 3;
    for (int oc = blockIdx.x * 4 + w; oc < noct; oc += gridDim.x * 4) {
        int r0 = oc * 8;
        #pragma unroll
        for (int k = 0; k < 8; k++) {
            int rr = r0 + k;
            *(float4*)&s_row[w][k][f4] =
                (rr < Nrows) ? *(const float4*)&r[(size_t)rr * NAB + f4] : z4;
        }
        __syncwarp();
        ull acc[8][2];
        #pragma unroll
        for (int k = 0; k < 8; k++) { acc[k][0] = 0ull; acc[k][1] = 0ull; }
        #pragma unroll 4
        for (int kk = 0; kk < NAB; kk++) {
            float4 wv = __ldg((const float4*)&Waf[kk * NAB + f4]);
            ull w01 = pk2(wv.x, wv.y);
            ull w23 = pk2(wv.z, wv.w);
            #pragma unroll
            for (int k = 0; k < 8; k++) {
                float x = s_row[w][k][kk];
                ull hv = pk2(x, x);
                acc[k][0] = fma2(w01, hv, acc[k][0]);
                acc[k][1] = fma2(w23, hv, acc[k][1]);
            }
        }
        #pragma unroll
        for (int k = 0; k < 8; k++) {
            int rr = r0 + k;
            if (rr < Nrows) {
                float2 v01 = up2(acc[k][0]);
                float2 v23 = up2(acc[k][1]);
                __half2 h0 = __floats2half2_rn(v01.x, v01.y);
                __half2 h1 = __floats2half2_rn(v23.x, v23.y);
                uint2 packed;
                packed.x = *(unsigned*)&h0;
                packed.y = *(unsigned*)&h1;
                *(uint2*)&g_rf16[(size_t)rr * NAB + f4] = packed;
            }
        }
        __syncwarp();
    }
}

// ---------------------------------------------------------------------------
// Build ef(e) table in fp16: one block per row, exact reference math.
// ---------------------------------------------------------------------------
__global__ void __launch_bounds__(128) k_table(const float* __restrict__ W1,
                                               const float* __restrict__ b1,
                                               const float* __restrict__ W2,
                                               const float* __restrict__ b2) {
    __shared__ float s_g[NG];
    __shared__ float s_h1[NG];
    const int row = blockIdx.x;
    const int tid = threadIdx.x;
    const float kWidth = 5.0f / 49.0f;
    const float kCoeff = -0.5f / (kWidth * kWidth);
    const float e = (float)row * (5.0f / (float)TBN);

    if (tid < NG) {
        float d = e - (float)tid * kWidth;
        s_g[tid] = __expf(kCoeff * d * d);
    }
    __syncthreads();
    if (tid < NG) {
        float acc = b1[tid];
        #pragma unroll 10
        for (int i = 0; i < NG; i++)
            acc += s_g[i] * __ldg(&W1[i * NG + tid]);
        s_h1[tid] = sspf(acc);
    }
    __syncthreads();
    float acc = b2[tid];
    #pragma unroll 10
    for (int j = 0; j < NG; j++)
        acc += s_h1[j] * __ldg(&W2[j * NAB + tid]);
    g_tab16[(size_t)row * NAB + tid] = __float2half_rn(acc);
}

// ---------------------------------------------------------------------------
// Edge kernel: fp16 table lerp -> fp16 rf gather -> fp32 float4 atomics.
// At the chip LTS cap (2.0 KB/edge); do not add bytes.
// ---------------------------------------------------------------------------
__device__ __forceinline__ float4 h4load(const __half* p) {
    uint2 raw = *(const uint2*)p;
    float2 lo = __half22float2(*(__half2*)&raw.x);
    float2 hi = __half22float2(*(__half2*)&raw.y);
    return make_float4(lo.x, lo.y, hi.x, hi.y);
}

__global__ void __launch_bounds__(256) k_edge2(const float* __restrict__ e_arr,
                                               const int* __restrict__ a_arr,
                                               int E) {
    const int lane = threadIdx.x & 31;
    const int fb   = lane * 4;
    const int gw   = (blockIdx.x * 256 + threadIdx.x) >> 5;
    const int nw   = (gridDim.x * 256) >> 5;
    const float invD = (float)TBN / 5.0f;

    for (int base = gw * 4; base < E; base += nw * 4) {
        int   nv = min(4, E - base);
        float fr[4]; int i0[4], ss[4], dd[4];
        #pragma unroll
        for (int k = 0; k < 4; k++) {
            int ei = (k < nv) ? base + k : base;
            float ev = __ldg(&e_arr[ei]);
            ss[k] = __ldg(&a_arr[2 * ei]);
            dd[k] = __ldg(&a_arr[2 * ei + 1]);
            float t = ev * invD;
            int   i = (int)t;
            i = i < TBN - 1 ? i : TBN - 1;
            i0[k] = i;
            fr[k] = t - (float)i;
        }
        float4 t0[4], t1[4], rs[4], rd[4];
        #pragma unroll
        for (int k = 0; k < 4; k++) {
            t0[k] = h4load(&g_tab16[(size_t)i0[k] * NAB + fb]);
            t1[k] = h4load(&g_tab16[(size_t)(i0[k] + 1) * NAB + fb]);
            rs[k] = h4load(&g_rf16[(size_t)ss[k] * NAB + fb]);
            rd[k] = h4load(&g_rf16[(size_t)dd[k] * NAB + fb]);
        }
        #pragma unroll
        for (int k = 0; k < 4; k++) {
            if (k < nv) {
                float4 ef;
                ef.x = t0[k].x + fr[k] * (t1[k].x - t0[k].x);
                ef.y = t0[k].y + fr[k] * (t1[k].y - t0[k].y);
                ef.z = t0[k].z + fr[k] * (t1[k].z - t0[k].z);
                ef.w = t0[k].w + fr[k] * (t1[k].w - t0[k].w);
                float4 m1 = make_float4(rs[k].x * ef.x, rs[k].y * ef.y,
                                        rs[k].z * ef.z, rs[k].w * ef.w);
                float4 m2 = make_float4(rd[k].x * ef.x, rd[k].y * ef.y,
                                        rd[k].z * ef.z, rd[k].w * ef.w);
                atomicAdd((float4*)&g_agg[(size_t)dd[k] * NAB + fb], m1);
                atomicAdd((float4*)&g_agg[(size_t)ss[k] * NAB + fb], m2);
            }
        }
    }
}

// ---------------------------------------------------------------------------
// out = ssp(agg @ W_d1 + b_d1) @ W_d2 + b_d2.  8 rows/warp, f32x2 FMA.
// ---------------------------------------------------------------------------
__global__ void __launch_bounds__(128) k_out(const float* __restrict__ W1,
                                             const float* __restrict__ b1,
                                             const float* __restrict__ W2,
                                             const float* __restrict__ b2,
                                             float* __restrict__ out,
                                             int Nrows) {
    __shared__ __align__(16) float s_row[4][8][NAB];
    __shared__ __align__(16) float s_h[4][8][NAB];
    int w = threadIdx.x >> 5, l = threadIdx.x & 31;
    int f4 = l * 4;
    const float4 z4 = make_float4(0.f, 0.f, 0.f, 0.f);
    float4 bb1 = *(const float4*)&b1[f4];
    float4 bb2 = *(const float4*)&b2[f4];
    int noct = (Nrows + 7) >> 3;
    for (int oc = blockIdx.x * 4 + w; oc < noct; oc += gridDim.x * 4) {
        int r0 = oc * 8;
        #pragma unroll
        for (int k = 0; k < 8; k++) {
            int rr = r0 + k;
            *(float4*)&s_row[w][k][f4] =
                (rr < Nrows) ? *(const float4*)&g_agg[(size_t)rr * NAB + f4] : z4;
        }
        __syncwarp();
        ull acc[8][2];
        #pragma unroll
        for (int k = 0; k < 8; k++) {
            acc[k][0] = pk2(bb1.x, bb1.y);
            acc[k][1] = pk2(bb1.z, bb1.w);
        }
        #pragma unroll 4
        for (int kk = 0; kk < NAB; kk++) {
            float4 wv = __ldg((const float4*)&W1[kk * NAB + f4]);
            ull w01 = pk2(wv.x, wv.y);
            ull w23 = pk2(wv.z, wv.w);
            #pragma unroll
            for (int k = 0; k < 8; k++) {
                float x = s_row[w][k][kk];
                ull hv = pk2(x, x);
                acc[k][0] = fma2(w01, hv, acc[k][0]);
                acc[k][1] = fma2(w23, hv, acc[k][1]);
            }
        }
        #pragma unroll
        for (int k = 0; k < 8; k++) {
            float2 v01 = up2(acc[k][0]);
            float2 v23 = up2(acc[k][1]);
            s_h[w][k][f4 + 0] = sspf(v01.x);
            s_h[w][k][f4 + 1] = sspf(v01.y);
            s_h[w][k][f4 + 2] = sspf(v23.x);
            s_h[w][k][f4 + 3] = sspf(v23.y);
        }
        __syncwarp();
        ull cc[8][2];
        #pragma unroll
        for (int k = 0; k < 8; k++) {
            cc[k][0] = pk2(bb2.x, bb2.y);
            cc[k][1] = pk2(bb2.z, bb2.w);
        }
        #pragma unroll 4
        for (int j = 0; j < NAB; j++) {
            float4 wv = __ldg((const float4*)&W2[j * NAB + f4]);
            ull w01 = pk2(wv.x, wv.y);
            ull w23 = pk2(wv.z, wv.w);
            #pragma unroll
            for (int k = 0; k < 8; k++) {
                float x = s_h[w][k][j];
                ull hv = pk2(x, x);
                cc[k][0] = fma2(w01, hv, cc[k][0]);
                cc[k][1] = fma2(w23, hv, cc[k][1]);
            }
        }
        #pragma unroll
        for (int k = 0; k < 8; k++) {
            int rr = r0 + k;
            if (rr < Nrows) {
                float2 v01 = up2(cc[k][0]);
                float2 v23 = up2(cc[k][1]);
                *(float4*)&out[(size_t)rr * NAB + f4] =
                    make_float4(v01.x, v01.y, v23.x, v23.y);
            }
        }
        __syncwarp();
    }
}

__global__ void k_noop() {}

// ---------------------------------------------------------------------------
extern "C" void kernel_launch(void* const* d_in, const int* in_sizes, int n_in,
                              void* d_out, int out_size) {
    const float* r     = (const float*)d_in[0];
    const float* e     = (const float*)d_in[1];
    const int*   a     = (const int*)d_in[2];
    const float* W_df1 = (const float*)d_in[3];
    const float* b_df1 = (const float*)d_in[4];
    const float* W_df2 = (const float*)d_in[5];
    const float* b_df2 = (const float*)d_in[6];
    const float* W_af  = (const float*)d_in[7];
    const float* W_d1  = (const float*)d_in[8];
    const float* b_d1  = (const float*)d_in[9];
    const float* W_d2  = (const float*)d_in[10];
    const float* b_d2  = (const float*)d_in[11];
    float* out = (float*)d_out;

    int N = in_sizes[0] / NAB;
    int E = in_sizes[1];

    // agg zeroing via DMA engine (memset node, not a kernel launch)
    void* agg_ptr = nullptr;
    cudaGetSymbolAddress(&agg_ptr, g_agg);
    cudaMemsetAsync(agg_ptr, 0, (size_t)N * NAB * sizeof(float), 0);

    int noct    = (N + 7) >> 3;
    int grid_rc = (noct + 3) / 4;

    // 5 kernel launches/iter; profiled global launch L=3 -> k_out this round
    k_rf<<<grid_rc, 128>>>(r, W_af, N);                          // 0
    k_table<<<TBN + 1, 128>>>(W_df1, b_df1, W_df2, b_df2);       // 1
    int nwork  = (E + 31) / 32;
    int grid_e = nwork < 2368 ? nwork : 2368;
    k_edge2<<<grid_e, 256>>>(e, a, E);                           // 2
    k_out<<<grid_rc, 128>>>(W_d1, b_d1, W_d2, b_d2, out, N);     // 3
    k_noop<<<1, 32>>>();                                         // 4
}

// round 10
// speedup vs baseline: 1.0217x; 1.0217x over previous
#include <cuda_runtime.h>
#include <cuda_fp16.h>
#include <cstdint>

#define NAB       128
#define NG        50
#define TBN       4096             // table intervals over [0, CUTOFF]
#define MAX_ATOMS 50000

typedef unsigned long long ull;

__device__ __align__(16) __half g_rf16[(size_t)MAX_ATOMS * NAB];     // 12.8 MB
__device__ __align__(16) float  g_agg[(size_t)MAX_ATOMS * NAB];      // 25.6 MB
__device__ __align__(16) __half g_tab16[(size_t)(TBN + 1) * NAB];    // 1 MB

__device__ __forceinline__ float sspf(float x) {
    return fmaxf(x, 0.0f) + log1pf(__expf(-fabsf(x))) - 0.6931471805599453f;
}

// ---- packed f32x2 helpers (sm_100+) ---------------------------------------
__device__ __forceinline__ ull pk2(float lo, float hi) {
    ull r; asm("mov.b64 %0, {%1, %2};" : "=l"(r) : "f"(lo), "f"(hi)); return r;
}
__device__ __forceinline__ ull fma2(ull a, ull b, ull c) {
    ull d; asm("fma.rn.f32x2 %0, %1, %2, %3;" : "=l"(d) : "l"(a), "l"(b), "l"(c));
    return d;
}
__device__ __forceinline__ float2 up2(ull v) {
    float2 f; asm("mov.b64 {%0, %1}, %2;" : "=f"(f.x), "=f"(f.y) : "l"(v));
    return f;
}

// ---------------------------------------------------------------------------
// Fused prep: blocks [0, TBN+1) build the fp16 ef-table (exact reference
// math); remaining blocks compute rf = r @ W_af (fp16 out) + zero g_agg.
// 4 rows/warp, f32x2 FMA (round-8 measured-best shape).
// ---------------------------------------------------------------------------
__global__ void __launch_bounds__(128) k_prep(const float* __restrict__ r,
                                              const float* __restrict__ Waf,
                                              const float* __restrict__ W1,
                                              const float* __restrict__ b1,
                                              const float* __restrict__ W2,
                                              const float* __restrict__ b2,
                                              int Nrows) {
    const int tid = threadIdx.x;
    if (blockIdx.x < TBN + 1) {
        // ---- table branch ----
        __shared__ float s_g[NG];
        __shared__ float s_h1[NG];
        const int row = blockIdx.x;
        const float kWidth = 5.0f / 49.0f;
        const float kCoeff = -0.5f / (kWidth * kWidth);
        const float e = (float)row * (5.0f / (float)TBN);
        if (tid < NG) {
            float d = e - (float)tid * kWidth;
            s_g[tid] = __expf(kCoeff * d * d);
        }
        __syncthreads();
        if (tid < NG) {
            float acc = b1[tid];
            #pragma unroll 10
            for (int i = 0; i < NG; i++)
                acc += s_g[i] * __ldg(&W1[i * NG + tid]);
            s_h1[tid] = sspf(acc);
        }
        __syncthreads();
        float acc = b2[tid];
        #pragma unroll 10
        for (int j = 0; j < NG; j++)
            acc += s_h1[j] * __ldg(&W2[j * NAB + tid]);
        g_tab16[(size_t)row * NAB + tid] = __float2half_rn(acc);
        return;
    }
    // ---- rf branch ----
    __shared__ __align__(16) float s_row[4][4][NAB];
    const int bid = blockIdx.x - (TBN + 1);
    const int nrb = gridDim.x - (TBN + 1);
    int w = tid >> 5, l = tid & 31;
    int f4 = l * 4;
    const float4 z4 = make_float4(0.f, 0.f, 0.f, 0.f);
    int nquads = (Nrows + 3) >> 2;
    for (int qd = bid * 4 + w; qd < nquads; qd += nrb * 4) {
        int r0 = qd * 4;
        #pragma unroll
        for (int k = 0; k < 4; k++) {
            int rr = r0 + k;
            *(float4*)&s_row[w][k][f4] =
                (rr < Nrows) ? *(const float4*)&r[(size_t)rr * NAB + f4] : z4;
        }
        __syncwarp();
        ull acc[4][2];
        #pragma unroll
        for (int k = 0; k < 4; k++) { acc[k][0] = 0ull; acc[k][1] = 0ull; }
        #pragma unroll 4
        for (int kk = 0; kk < NAB; kk++) {
            float4 wv = __ldg((const float4*)&Waf[kk * NAB + f4]);
            ull w01 = pk2(wv.x, wv.y);
            ull w23 = pk2(wv.z, wv.w);
            #pragma unroll
            for (int k = 0; k < 4; k++) {
                float x = s_row[w][k][kk];
                ull hv = pk2(x, x);
                acc[k][0] = fma2(w01, hv, acc[k][0]);
                acc[k][1] = fma2(w23, hv, acc[k][1]);
            }
        }
        #pragma unroll
        for (int k = 0; k < 4; k++) {
            int rr = r0 + k;
            if (rr < Nrows) {
                float2 v01 = up2(acc[k][0]);
                float2 v23 = up2(acc[k][1]);
                __half2 h0 = __floats2half2_rn(v01.x, v01.y);
                __half2 h1 = __floats2half2_rn(v23.x, v23.y);
                uint2 packed;
                packed.x = *(unsigned*)&h0;
                packed.y = *(unsigned*)&h1;
                *(uint2*)&g_rf16[(size_t)rr * NAB + f4] = packed;
                *(float4*)&g_agg[(size_t)rr * NAB + f4] = z4;
            }
        }
        __syncwarp();
    }
}

// ---------------------------------------------------------------------------
// Edge kernel: fp16 table lerp -> fp16 rf gather -> fp32 float4 atomics.
// At the chip LTS cap (2.0 KB/edge); do not add bytes.
// ---------------------------------------------------------------------------
__device__ __forceinline__ float4 h4load(const __half* p) {
    uint2 raw = *(const uint2*)p;
    float2 lo = __half22float2(*(__half2*)&raw.x);
    float2 hi = __half22float2(*(__half2*)&raw.y);
    return make_float4(lo.x, lo.y, hi.x, hi.y);
}

__global__ void __launch_bounds__(256) k_edge2(const float* __restrict__ e_arr,
                                               const int* __restrict__ a_arr,
                                               int E) {
    const int lane = threadIdx.x & 31;
    const int fb   = lane * 4;
    const int gw   = (blockIdx.x * 256 + threadIdx.x) >> 5;
    const int nw   = (gridDim.x * 256) >> 5;
    const float invD = (float)TBN / 5.0f;

    for (int base = gw * 4; base < E; base += nw * 4) {
        int   nv = min(4, E - base);
        float fr[4]; int i0[4], ss[4], dd[4];
        #pragma unroll
        for (int k = 0; k < 4; k++) {
            int ei = (k < nv) ? base + k : base;
            float ev = __ldg(&e_arr[ei]);
            ss[k] = __ldg(&a_arr[2 * ei]);
            dd[k] = __ldg(&a_arr[2 * ei + 1]);
            float t = ev * invD;
            int   i = (int)t;
            i = i < TBN - 1 ? i : TBN - 1;
            i0[k] = i;
            fr[k] = t - (float)i;
        }
        float4 t0[4], t1[4], rs[4], rd[4];
        #pragma unroll
        for (int k = 0; k < 4; k++) {
            t0[k] = h4load(&g_tab16[(size_t)i0[k] * NAB + fb]);
            t1[k] = h4load(&g_tab16[(size_t)(i0[k] + 1) * NAB + fb]);
            rs[k] = h4load(&g_rf16[(size_t)ss[k] * NAB + fb]);
            rd[k] = h4load(&g_rf16[(size_t)dd[k] * NAB + fb]);
        }
        #pragma unroll
        for (int k = 0; k < 4; k++) {
            if (k < nv) {
                float4 ef;
                ef.x = t0[k].x + fr[k] * (t1[k].x - t0[k].x);
                ef.y = t0[k].y + fr[k] * (t1[k].y - t0[k].y);
                ef.z = t0[k].z + fr[k] * (t1[k].z - t0[k].z);
                ef.w = t0[k].w + fr[k] * (t1[k].w - t0[k].w);
                float4 m1 = make_float4(rs[k].x * ef.x, rs[k].y * ef.y,
                                        rs[k].z * ef.z, rs[k].w * ef.w);
                float4 m2 = make_float4(rd[k].x * ef.x, rd[k].y * ef.y,
                                        rd[k].z * ef.z, rd[k].w * ef.w);
                atomicAdd((float4*)&g_agg[(size_t)dd[k] * NAB + fb], m1);
                atomicAdd((float4*)&g_agg[(size_t)ss[k] * NAB + fb], m2);
            }
        }
    }
}

// ---------------------------------------------------------------------------
// out = ssp(agg @ W_d1 + b_d1) @ W_d2 + b_d2.  4 rows/warp, f32x2 FMA.
// ---------------------------------------------------------------------------
__global__ void __launch_bounds__(128, 8) k_out(const float* __restrict__ W1,
                                                const float* __restrict__ b1,
                                                const float* __restrict__ W2,
                                                const float* __restrict__ b2,
                                                float* __restrict__ out,
                                                int Nrows) {
    __shared__ __align__(16) float s_row[4][4][NAB];
    __shared__ __align__(16) float s_h[4][4][NAB];
    int w = threadIdx.x >> 5, l = threadIdx.x & 31;
    int f4 = l * 4;
    const float4 z4 = make_float4(0.f, 0.f, 0.f, 0.f);
    float4 bb1 = *(const float4*)&b1[f4];
    float4 bb2 = *(const float4*)&b2[f4];
    int nquads = (Nrows + 3) >> 2;
    for (int qd = blockIdx.x * 4 + w; qd < nquads; qd += gridDim.x * 4) {
        int r0 = qd * 4;
        #pragma unroll
        for (int k = 0; k < 4; k++) {
            int rr = r0 + k;
            *(float4*)&s_row[w][k][f4] =
                (rr < Nrows) ? *(const float4*)&g_agg[(size_t)rr * NAB + f4] : z4;
        }
        __syncwarp();
        ull acc[4][2];
        #pragma unroll
        for (int k = 0; k < 4; k++) {
            acc[k][0] = pk2(bb1.x, bb1.y);
            acc[k][1] = pk2(bb1.z, bb1.w);
        }
        #pragma unroll 4
        for (int kk = 0; kk < NAB; kk++) {
            float4 wv = __ldg((const float4*)&W1[kk * NAB + f4]);
            ull w01 = pk2(wv.x, wv.y);
            ull w23 = pk2(wv.z, wv.w);
            #pragma unroll
            for (int k = 0; k < 4; k++) {
                float x = s_row[w][k][kk];
                ull hv = pk2(x, x);
                acc[k][0] = fma2(w01, hv, acc[k][0]);
                acc[k][1] = fma2(w23, hv, acc[k][1]);
            }
        }
        #pragma unroll
        for (int k = 0; k < 4; k++) {
            float2 v01 = up2(acc[k][0]);
            float2 v23 = up2(acc[k][1]);
            s_h[w][k][f4 + 0] = sspf(v01.x);
            s_h[w][k][f4 + 1] = sspf(v01.y);
            s_h[w][k][f4 + 2] = sspf(v23.x);
            s_h[w][k][f4 + 3] = sspf(v23.y);
        }
        __syncwarp();
        ull cc[4][2];
        #pragma unroll
        for (int k = 0; k < 4; k++) {
            cc[k][0] = pk2(bb2.x, bb2.y);
            cc[k][1] = pk2(bb2.z, bb2.w);
        }
        #pragma unroll 4
        for (int j = 0; j < NAB; j++) {
            float4 wv = __ldg((const float4*)&W2[j * NAB + f4]);
            ull w01 = pk2(wv.x, wv.y);
            ull w23 = pk2(wv.z, wv.w);
            #pragma unroll
            for (int k = 0; k < 4; k++) {
                float x = s_h[w][k][j];
                ull hv = pk2(x, x);
                cc[k][0] = fma2(w01, hv, cc[k][0]);
                cc[k][1] = fma2(w23, hv, cc[k][1]);
            }
        }
        #pragma unroll
        for (int k = 0; k < 4; k++) {
            int rr = r0 + k;
            if (rr < Nrows) {
                float2 v01 = up2(cc[k][0]);
                float2 v23 = up2(cc[k][1]);
                *(float4*)&out[(size_t)rr * NAB + f4] =
                    make_float4(v01.x, v01.y, v23.x, v23.y);
            }
        }
        __syncwarp();
    }
}

__global__ void k_noop() {}

// ---------------------------------------------------------------------------
extern "C" void kernel_launch(void* const* d_in, const int* in_sizes, int n_in,
                              void* d_out, int out_size) {
    const float* r     = (const float*)d_in[0];
    const float* e     = (const float*)d_in[1];
    const int*   a     = (const int*)d_in[2];
    const float* W_df1 = (const float*)d_in[3];
    const float* b_df1 = (const float*)d_in[4];
    const float* W_df2 = (const float*)d_in[5];
    const float* b_df2 = (const float*)d_in[6];
    const float* W_af  = (const float*)d_in[7];
    const float* W_d1  = (const float*)d_in[8];
    const float* b_d1  = (const float*)d_in[9];
    const float* W_d2  = (const float*)d_in[10];
    const float* b_d2  = (const float*)d_in[11];
    float* out = (float*)d_out;

    int N = in_sizes[0] / NAB;
    int E = in_sizes[1];

    int nquads  = (N + 3) >> 2;
    int grid_rf = (nquads + 3) / 4;

    // 5 kernel launches/iter; profiled global launch L=3 -> k_out
    k_prep<<<(TBN + 1) + grid_rf, 128>>>(r, W_af, W_df1, b_df1,
                                         W_df2, b_df2, N);       // 0
    k_noop<<<1, 32>>>();                                         // 1
    int nwork  = (E + 31) / 32;
    int grid_e = nwork < 2368 ? nwork : 2368;
    k_edge2<<<grid_e, 256>>>(e, a, E);                           // 2
    k_out<<<grid_rf, 128>>>(W_d1, b_d1, W_d2, b_d2, out, N);     // 3
    k_noop<<<1, 32>>>();                                         // 4
}

// round 11
// speedup vs baseline: 1.0566x; 1.0342x over previous
#include <cuda_runtime.h>
#include <cuda_fp16.h>
#include <cstdint>

#define NAB       128
#define NG        50
#define TBN       4096             // table intervals over [0, CUTOFF]
#define MAX_ATOMS 50000

typedef unsigned long long ull;

__device__ __align__(16) __half g_rf16[(size_t)MAX_ATOMS * NAB];     // 12.8 MB
__device__ __align__(16) float  g_agg[(size_t)MAX_ATOMS * NAB];      // 25.6 MB
__device__ __align__(16) __half g_tab16[(size_t)(TBN + 1) * NAB];    // 1 MB

__device__ __forceinline__ float sspf(float x) {
    return fmaxf(x, 0.0f) + log1pf(__expf(-fabsf(x))) - 0.6931471805599453f;
}

// ---- packed f32x2 helpers (sm_100+) ---------------------------------------
__device__ __forceinline__ ull pk2(float lo, float hi) {
    ull r; asm("mov.b64 %0, {%1, %2};" : "=l"(r) : "f"(lo), "f"(hi)); return r;
}
__device__ __forceinline__ ull fma2(ull a, ull b, ull c) {
    ull d; asm("fma.rn.f32x2 %0, %1, %2, %3;" : "=l"(d) : "l"(a), "l"(b), "l"(c));
    return d;
}
__device__ __forceinline__ float2 up2(ull v) {
    float2 f; asm("mov.b64 {%0, %1}, %2;" : "=f"(f.x), "=f"(f.y) : "l"(v));
    return f;
}

// ---------------------------------------------------------------------------
// rf = r @ W_af (stored fp16) AND zero g_agg.  4 rows/warp, dup-packed smem
// activations (LDS.128 per 2 k-steps), direct ulonglong2 weight loads.
// ---------------------------------------------------------------------------
__global__ void __launch_bounds__(128) k_rf(const float* __restrict__ r,
                                            const float* __restrict__ Waf,
                                            int Nrows) {
    __shared__ __align__(16) ull s_rowp[4][4][NAB];   // (x,x) duplicated pairs
    int w = threadIdx.x >> 5, l = threadIdx.x & 31;
    int f4 = l * 4;
    const float4 z4 = make_float4(0.f, 0.f, 0.f, 0.f);
    int nquads = (Nrows + 3) >> 2;
    for (int qd = blockIdx.x * 4 + w; qd < nquads; qd += gridDim.x * 4) {
        int r0 = qd * 4;
        #pragma unroll
        for (int k = 0; k < 4; k++) {
            int rr = r0 + k;
            float4 rv = (rr < Nrows) ? *(const float4*)&r[(size_t)rr * NAB + f4] : z4;
            ulonglong2 p0; p0.x = pk2(rv.x, rv.x); p0.y = pk2(rv.y, rv.y);
            ulonglong2 p1; p1.x = pk2(rv.z, rv.z); p1.y = pk2(rv.w, rv.w);
            *(ulonglong2*)&s_rowp[w][k][f4]     = p0;
            *(ulonglong2*)&s_rowp[w][k][f4 + 2] = p1;
        }
        __syncwarp();
        ull acc[4][2];
        #pragma unroll
        for (int k = 0; k < 4; k++) { acc[k][0] = 0ull; acc[k][1] = 0ull; }
        #pragma unroll 4
        for (int kk = 0; kk < NAB; kk += 2) {
            ulonglong2 wA = __ldg((const ulonglong2*)&Waf[kk * NAB + f4]);
            ulonglong2 wB = __ldg((const ulonglong2*)&Waf[(kk + 1) * NAB + f4]);
            #pragma unroll
            for (int k = 0; k < 4; k++) {
                ulonglong2 xx = *(const ulonglong2*)&s_rowp[w][k][kk]; // uniform
                acc[k][0] = fma2(wA.x, xx.x, acc[k][0]);
                acc[k][1] = fma2(wA.y, xx.x, acc[k][1]);
                acc[k][0] = fma2(wB.x, xx.y, acc[k][0]);
                acc[k][1] = fma2(wB.y, xx.y, acc[k][1]);
            }
        }
        #pragma unroll
        for (int k = 0; k < 4; k++) {
            int rr = r0 + k;
            if (rr < Nrows) {
                float2 v01 = up2(acc[k][0]);
                float2 v23 = up2(acc[k][1]);
                __half2 h0 = __floats2half2_rn(v01.x, v01.y);
                __half2 h1 = __floats2half2_rn(v23.x, v23.y);
                uint2 packed;
                packed.x = *(unsigned*)&h0;
                packed.y = *(unsigned*)&h1;
                *(uint2*)&g_rf16[(size_t)rr * NAB + f4] = packed;
                *(float4*)&g_agg[(size_t)rr * NAB + f4] = z4;
            }
        }
        __syncwarp();
    }
}

// ---------------------------------------------------------------------------
// Build ef(e) table in fp16: one block per row, exact reference math.
// ---------------------------------------------------------------------------
__global__ void __launch_bounds__(128) k_table(const float* __restrict__ W1,
                                               const float* __restrict__ b1,
                                               const float* __restrict__ W2,
                                               const float* __restrict__ b2) {
    __shared__ float s_g[NG];
    __shared__ float s_h1[NG];
    const int row = blockIdx.x;
    const int tid = threadIdx.x;
    const float kWidth = 5.0f / 49.0f;
    const float kCoeff = -0.5f / (kWidth * kWidth);
    const float e = (float)row * (5.0f / (float)TBN);

    if (tid < NG) {
        float d = e - (float)tid * kWidth;
        s_g[tid] = __expf(kCoeff * d * d);
    }
    __syncthreads();
    if (tid < NG) {
        float acc = b1[tid];
        #pragma unroll 10
        for (int i = 0; i < NG; i++)
            acc += s_g[i] * __ldg(&W1[i * NG + tid]);
        s_h1[tid] = sspf(acc);
    }
    __syncthreads();
    float acc = b2[tid];
    #pragma unroll 10
    for (int j = 0; j < NG; j++)
        acc += s_h1[j] * __ldg(&W2[j * NAB + tid]);
    g_tab16[(size_t)row * NAB + tid] = __float2half_rn(acc);
}

// ---------------------------------------------------------------------------
// Edge kernel: fp16 table lerp -> fp16 rf gather -> fp32 float4 atomics.
// At the chip LTS cap (2.0 KB/edge); unchanged.
// ---------------------------------------------------------------------------
__device__ __forceinline__ float4 h4load(const __half* p) {
    uint2 raw = *(const uint2*)p;
    float2 lo = __half22float2(*(__half2*)&raw.x);
    float2 hi = __half22float2(*(__half2*)&raw.y);
    return make_float4(lo.x, lo.y, hi.x, hi.y);
}

__global__ void __launch_bounds__(256) k_edge2(const float* __restrict__ e_arr,
                                               const int* __restrict__ a_arr,
                                               int E) {
    const int lane = threadIdx.x & 31;
    const int fb   = lane * 4;
    const int gw   = (blockIdx.x * 256 + threadIdx.x) >> 5;
    const int nw   = (gridDim.x * 256) >> 5;
    const float invD = (float)TBN / 5.0f;

    for (int base = gw * 4; base < E; base += nw * 4) {
        int   nv = min(4, E - base);
        float fr[4]; int i0[4], ss[4], dd[4];
        #pragma unroll
        for (int k = 0; k < 4; k++) {
            int ei = (k < nv) ? base + k : base;
            float ev = __ldg(&e_arr[ei]);
            ss[k] = __ldg(&a_arr[2 * ei]);
            dd[k] = __ldg(&a_arr[2 * ei + 1]);
            float t = ev * invD;
            int   i = (int)t;
            i = i < TBN - 1 ? i : TBN - 1;
            i0[k] = i;
            fr[k] = t - (float)i;
        }
        float4 t0[4], t1[4], rs[4], rd[4];
        #pragma unroll
        for (int k = 0; k < 4; k++) {
            t0[k] = h4load(&g_tab16[(size_t)i0[k] * NAB + fb]);
            t1[k] = h4load(&g_tab16[(size_t)(i0[k] + 1) * NAB + fb]);
            rs[k] = h4load(&g_rf16[(size_t)ss[k] * NAB + fb]);
            rd[k] = h4load(&g_rf16[(size_t)dd[k] * NAB + fb]);
        }
        #pragma unroll
        for (int k = 0; k < 4; k++) {
            if (k < nv) {
                float4 ef;
                ef.x = t0[k].x + fr[k] * (t1[k].x - t0[k].x);
                ef.y = t0[k].y + fr[k] * (t1[k].y - t0[k].y);
                ef.z = t0[k].z + fr[k] * (t1[k].z - t0[k].z);
                ef.w = t0[k].w + fr[k] * (t1[k].w - t0[k].w);
                float4 m1 = make_float4(rs[k].x * ef.x, rs[k].y * ef.y,
                                        rs[k].z * ef.z, rs[k].w * ef.w);
                float4 m2 = make_float4(rd[k].x * ef.x, rd[k].y * ef.y,
                                        rd[k].z * ef.z, rd[k].w * ef.w);
                atomicAdd((float4*)&g_agg[(size_t)dd[k] * NAB + fb], m1);
                atomicAdd((float4*)&g_agg[(size_t)ss[k] * NAB + fb], m2);
            }
        }
    }
}

// ---------------------------------------------------------------------------
// out = ssp(agg @ W_d1 + b_d1) @ W_d2 + b_d2.  4 rows/warp, dup-packed smem,
// direct ulonglong2 weight loads, no min-blocks clamp.
// ---------------------------------------------------------------------------
__global__ void __launch_bounds__(128) k_out(const float* __restrict__ W1,
                                             const float* __restrict__ b1,
                                             const float* __restrict__ W2,
                                             const float* __restrict__ b2,
                                             float* __restrict__ out,
                                             int Nrows) {
    __shared__ __align__(16) ull s_rowp[4][4][NAB];
    __shared__ __align__(16) ull s_hp[4][4][NAB];
    int w = threadIdx.x >> 5, l = threadIdx.x & 31;
    int f4 = l * 4;
    const float4 z4 = make_float4(0.f, 0.f, 0.f, 0.f);
    float4 bb1 = *(const float4*)&b1[f4];
    float4 bb2 = *(const float4*)&b2[f4];
    ull b1p0 = pk2(bb1.x, bb1.y), b1p1 = pk2(bb1.z, bb1.w);
    ull b2p0 = pk2(bb2.x, bb2.y), b2p1 = pk2(bb2.z, bb2.w);
    int nquads = (Nrows + 3) >> 2;
    for (int qd = blockIdx.x * 4 + w; qd < nquads; qd += gridDim.x * 4) {
        int r0 = qd * 4;
        #pragma unroll
        for (int k = 0; k < 4; k++) {
            int rr = r0 + k;
            float4 rv = (rr < Nrows) ? *(const float4*)&g_agg[(size_t)rr * NAB + f4] : z4;
            ulonglong2 p0; p0.x = pk2(rv.x, rv.x); p0.y = pk2(rv.y, rv.y);
            ulonglong2 p1; p1.x = pk2(rv.z, rv.z); p1.y = pk2(rv.w, rv.w);
            *(ulonglong2*)&s_rowp[w][k][f4]     = p0;
            *(ulonglong2*)&s_rowp[w][k][f4 + 2] = p1;
        }
        __syncwarp();
        ull acc[4][2];
        #pragma unroll
        for (int k = 0; k < 4; k++) { acc[k][0] = b1p0; acc[k][1] = b1p1; }
        #pragma unroll 4
        for (int kk = 0; kk < NAB; kk += 2) {
            ulonglong2 wA = __ldg((const ulonglong2*)&W1[kk * NAB + f4]);
            ulonglong2 wB = __ldg((const ulonglong2*)&W1[(kk + 1) * NAB + f4]);
            #pragma unroll
            for (int k = 0; k < 4; k++) {
                ulonglong2 xx = *(const ulonglong2*)&s_rowp[w][k][kk]; // uniform
                acc[k][0] = fma2(wA.x, xx.x, acc[k][0]);
                acc[k][1] = fma2(wA.y, xx.x, acc[k][1]);
                acc[k][0] = fma2(wB.x, xx.y, acc[k][0]);
                acc[k][1] = fma2(wB.y, xx.y, acc[k][1]);
            }
        }
        #pragma unroll
        for (int k = 0; k < 4; k++) {
            float2 v01 = up2(acc[k][0]);
            float2 v23 = up2(acc[k][1]);
            float s0 = sspf(v01.x), s1 = sspf(v01.y);
            float s2 = sspf(v23.x), s3 = sspf(v23.y);
            ulonglong2 p0; p0.x = pk2(s0, s0); p0.y = pk2(s1, s1);
            ulonglong2 p1; p1.x = pk2(s2, s2); p1.y = pk2(s3, s3);
            *(ulonglong2*)&s_hp[w][k][f4]     = p0;
            *(ulonglong2*)&s_hp[w][k][f4 + 2] = p1;
        }
        __syncwarp();
        ull cc[4][2];
        #pragma unroll
        for (int k = 0; k < 4; k++) { cc[k][0] = b2p0; cc[k][1] = b2p1; }
        #pragma unroll 4
        for (int j = 0; j < NAB; j += 2) {
            ulonglong2 wA = __ldg((const ulonglong2*)&W2[j * NAB + f4]);
            ulonglong2 wB = __ldg((const ulonglong2*)&W2[(j + 1) * NAB + f4]);
            #pragma unroll
            for (int k = 0; k < 4; k++) {
                ulonglong2 xx = *(const ulonglong2*)&s_hp[w][k][j];    // uniform
                cc[k][0] = fma2(wA.x, xx.x, cc[k][0]);
                cc[k][1] = fma2(wA.y, xx.x, cc[k][1]);
                cc[k][0] = fma2(wB.x, xx.y, cc[k][0]);
                cc[k][1] = fma2(wB.y, xx.y, cc[k][1]);
            }
        }
        #pragma unroll
        for (int k = 0; k < 4; k++) {
            int rr = r0 + k;
            if (rr < Nrows) {
                float2 v01 = up2(cc[k][0]);
                float2 v23 = up2(cc[k][1]);
                *(float4*)&out[(size_t)rr * NAB + f4] =
                    make_float4(v01.x, v01.y, v23.x, v23.y);
            }
        }
        __syncwarp();
    }
}

__global__ void k_noop() {}

// ---------------------------------------------------------------------------
extern "C" void kernel_launch(void* const* d_in, const int* in_sizes, int n_in,
                              void* d_out, int out_size) {
    const float* r     = (const float*)d_in[0];
    const float* e     = (const float*)d_in[1];
    const int*   a     = (const int*)d_in[2];
    const float* W_df1 = (const float*)d_in[3];
    const float* b_df1 = (const float*)d_in[4];
    const float* W_df2 = (const float*)d_in[5];
    const float* b_df2 = (const float*)d_in[6];
    const float* W_af  = (const float*)d_in[7];
    const float* W_d1  = (const float*)d_in[8];
    const float* b_d1  = (const float*)d_in[9];
    const float* W_d2  = (const float*)d_in[10];
    const float* b_d2  = (const float*)d_in[11];
    float* out = (float*)d_out;

    int N = in_sizes[0] / NAB;
    int E = in_sizes[1];

    int nquads  = (N + 3) >> 2;
    int grid_rc = (nquads + 3) / 4;

    // 5 kernel launches/iter; profiled global launch L=3 -> k_out
    k_rf<<<grid_rc, 128>>>(r, W_af, N);                          // 0
    k_table<<<TBN + 1, 128>>>(W_df1, b_df1, W_df2, b_df2);       // 1
    int nwork  = (E + 31) / 32;
    int grid_e = nwork < 2368 ? nwork : 2368;
    k_edge2<<<grid_e, 256>>>(e, a, E);                           // 2
    k_out<<<grid_rc, 128>>>(W_d1, b_d1, W_d2, b_d2, out, N);     // 3
    k_noop<<<1, 32>>>();                                         // 4
}

// round 12
// speedup vs baseline: 1.1075x; 1.0482x over previous
#include <cuda_runtime.h>
#include <cuda_fp16.h>
#include <cstdint>

#define NAB       128
#define NG        50
#define TBN       4096             // table intervals over [0, CUTOFF]
#define MAX_ATOMS 50000

typedef unsigned long long ull;

__device__ __align__(16) __half g_rf16[(size_t)MAX_ATOMS * NAB];     // 12.8 MB
__device__ __align__(16) float  g_agg[(size_t)MAX_ATOMS * NAB];      // 25.6 MB
__device__ __align__(16) __half g_tab16[(size_t)(TBN + 1) * NAB];    // 1 MB

__device__ __forceinline__ float sspf(float x) {
    return fmaxf(x, 0.0f) + log1pf(__expf(-fabsf(x))) - 0.6931471805599453f;
}

// ---- packed f32x2 helpers (sm_100+) ---------------------------------------
__device__ __forceinline__ ull pk2(float lo, float hi) {
    ull r; asm("mov.b64 %0, {%1, %2};" : "=l"(r) : "f"(lo), "f"(hi)); return r;
}
__device__ __forceinline__ ull fma2(ull a, ull b, ull c) {
    ull d; asm("fma.rn.f32x2 %0, %1, %2, %3;" : "=l"(d) : "l"(a), "l"(b), "l"(c));
    return d;
}
__device__ __forceinline__ float2 up2(ull v) {
    float2 f; asm("mov.b64 {%0, %1}, %2;" : "=f"(f.x), "=f"(f.y) : "l"(v));
    return f;
}

// ---------------------------------------------------------------------------
// rf = r @ W_af (stored fp16) AND zero g_agg.  4 rows/warp (round-8 shape),
// weights as direct ulonglong2 f32x2 operands.
// ---------------------------------------------------------------------------
__global__ void __launch_bounds__(128) k_rf(const float* __restrict__ r,
                                            const float* __restrict__ Waf,
                                            int Nrows) {
    __shared__ __align__(16) float s_row[4][4][NAB];
    int w = threadIdx.x >> 5, l = threadIdx.x & 31;
    int f4 = l * 4;
    const float4 z4 = make_float4(0.f, 0.f, 0.f, 0.f);
    int nquads = (Nrows + 3) >> 2;
    for (int qd = blockIdx.x * 4 + w; qd < nquads; qd += gridDim.x * 4) {
        int r0 = qd * 4;
        #pragma unroll
        for (int k = 0; k < 4; k++) {
            int rr = r0 + k;
            *(float4*)&s_row[w][k][f4] =
                (rr < Nrows) ? *(const float4*)&r[(size_t)rr * NAB + f4] : z4;
        }
        __syncwarp();
        ull acc[4][2];
        #pragma unroll
        for (int k = 0; k < 4; k++) { acc[k][0] = 0ull; acc[k][1] = 0ull; }
        #pragma unroll 4
        for (int kk = 0; kk < NAB; kk++) {
            ulonglong2 wv = __ldg((const ulonglong2*)&Waf[kk * NAB + f4]);
            #pragma unroll
            for (int k = 0; k < 4; k++) {
                float x = s_row[w][k][kk];          // uniform broadcast LDS
                ull hv = pk2(x, x);
                acc[k][0] = fma2(wv.x, hv, acc[k][0]);
                acc[k][1] = fma2(wv.y, hv, acc[k][1]);
            }
        }
        #pragma unroll
        for (int k = 0; k < 4; k++) {
            int rr = r0 + k;
            if (rr < Nrows) {
                float2 v01 = up2(acc[k][0]);
                float2 v23 = up2(acc[k][1]);
                __half2 h0 = __floats2half2_rn(v01.x, v01.y);
                __half2 h1 = __floats2half2_rn(v23.x, v23.y);
                uint2 packed;
                packed.x = *(unsigned*)&h0;
                packed.y = *(unsigned*)&h1;
                *(uint2*)&g_rf16[(size_t)rr * NAB + f4] = packed;
                *(float4*)&g_agg[(size_t)rr * NAB + f4] = z4;
            }
        }
        __syncwarp();
    }
}

// ---------------------------------------------------------------------------
// Build ef(e) table in fp16: one block per row, exact reference math.
// ---------------------------------------------------------------------------
__global__ void __launch_bounds__(128) k_table(const float* __restrict__ W1,
                                               const float* __restrict__ b1,
                                               const float* __restrict__ W2,
                                               const float* __restrict__ b2) {
    __shared__ float s_g[NG];
    __shared__ float s_h1[NG];
    const int row = blockIdx.x;
    const int tid = threadIdx.x;
    const float kWidth = 5.0f / 49.0f;
    const float kCoeff = -0.5f / (kWidth * kWidth);
    const float e = (float)row * (5.0f / (float)TBN);

    if (tid < NG) {
        float d = e - (float)tid * kWidth;
        s_g[tid] = __expf(kCoeff * d * d);
    }
    __syncthreads();
    if (tid < NG) {
        float acc = b1[tid];
        #pragma unroll 10
        for (int i = 0; i < NG; i++)
            acc += s_g[i] * __ldg(&W1[i * NG + tid]);
        s_h1[tid] = sspf(acc);
    }
    __syncthreads();
    float acc = b2[tid];
    #pragma unroll 10
    for (int j = 0; j < NG; j++)
        acc += s_h1[j] * __ldg(&W2[j * NAB + tid]);
    g_tab16[(size_t)row * NAB + tid] = __float2half_rn(acc);
}

// ---------------------------------------------------------------------------
// Edge kernel: fp16 table lerp -> fp16 rf gather -> fp32 float4 atomics.
// Pinned at the chip LTS cap (2.0 KB/edge, ~11.6 TB/s). Unchanged.
// ---------------------------------------------------------------------------
__device__ __forceinline__ float4 h4load(const __half* p) {
    uint2 raw = *(const uint2*)p;
    float2 lo = __half22float2(*(__half2*)&raw.x);
    float2 hi = __half22float2(*(__half2*)&raw.y);
    return make_float4(lo.x, lo.y, hi.x, hi.y);
}

__global__ void __launch_bounds__(256) k_edge2(const float* __restrict__ e_arr,
                                               const int* __restrict__ a_arr,
                                               int E) {
    const int lane = threadIdx.x & 31;
    const int fb   = lane * 4;
    const int gw   = (blockIdx.x * 256 + threadIdx.x) >> 5;
    const int nw   = (gridDim.x * 256) >> 5;
    const float invD = (float)TBN / 5.0f;

    for (int base = gw * 4; base < E; base += nw * 4) {
        int   nv = min(4, E - base);
        float fr[4]; int i0[4], ss[4], dd[4];
        #pragma unroll
        for (int k = 0; k < 4; k++) {
            int ei = (k < nv) ? base + k : base;
            float ev = __ldg(&e_arr[ei]);
            ss[k] = __ldg(&a_arr[2 * ei]);
            dd[k] = __ldg(&a_arr[2 * ei + 1]);
            float t = ev * invD;
            int   i = (int)t;
            i = i < TBN - 1 ? i : TBN - 1;
            i0[k] = i;
            fr[k] = t - (float)i;
        }
        float4 t0[4], t1[4], rs[4], rd[4];
        #pragma unroll
        for (int k = 0; k < 4; k++) {
            t0[k] = h4load(&g_tab16[(size_t)i0[k] * NAB + fb]);
            t1[k] = h4load(&g_tab16[(size_t)(i0[k] + 1) * NAB + fb]);
            rs[k] = h4load(&g_rf16[(size_t)ss[k] * NAB + fb]);
            rd[k] = h4load(&g_rf16[(size_t)dd[k] * NAB + fb]);
        }
        #pragma unroll
        for (int k = 0; k < 4; k++) {
            if (k < nv) {
                float4 ef;
                ef.x = t0[k].x + fr[k] * (t1[k].x - t0[k].x);
                ef.y = t0[k].y + fr[k] * (t1[k].y - t0[k].y);
                ef.z = t0[k].z + fr[k] * (t1[k].z - t0[k].z);
                ef.w = t0[k].w + fr[k] * (t1[k].w - t0[k].w);
                float4 m1 = make_float4(rs[k].x * ef.x, rs[k].y * ef.y,
                                        rs[k].z * ef.z, rs[k].w * ef.w);
                float4 m2 = make_float4(rd[k].x * ef.x, rd[k].y * ef.y,
                                        rd[k].z * ef.z, rd[k].w * ef.w);
                atomicAdd((float4*)&g_agg[(size_t)dd[k] * NAB + fb], m1);
                atomicAdd((float4*)&g_agg[(size_t)ss[k] * NAB + fb], m2);
            }
        }
    }
}

// ---------------------------------------------------------------------------
// out = ssp(agg @ W_d1 + b_d1) @ W_d2 + b_d2.  4 rows/warp (round-8 shape),
// weights as direct ulonglong2 f32x2 operands.
// ---------------------------------------------------------------------------
__global__ void __launch_bounds__(128) k_out(const float* __restrict__ W1,
                                             const float* __restrict__ b1,
                                             const float* __restrict__ W2,
                                             const float* __restrict__ b2,
                                             float* __restrict__ out,
                                             int Nrows) {
    __shared__ __align__(16) float s_row[4][4][NAB];
    __shared__ __align__(16) float s_h[4][4][NAB];
    int w = threadIdx.x >> 5, l = threadIdx.x & 31;
    int f4 = l * 4;
    const float4 z4 = make_float4(0.f, 0.f, 0.f, 0.f);
    float4 bb1 = *(const float4*)&b1[f4];
    float4 bb2 = *(const float4*)&b2[f4];
    ull b1p0 = pk2(bb1.x, bb1.y), b1p1 = pk2(bb1.z, bb1.w);
    ull b2p0 = pk2(bb2.x, bb2.y), b2p1 = pk2(bb2.z, bb2.w);
    int nquads = (Nrows + 3) >> 2;
    for (int qd = blockIdx.x * 4 + w; qd < nquads; qd += gridDim.x * 4) {
        int r0 = qd * 4;
        #pragma unroll
        for (int k = 0; k < 4; k++) {
            int rr = r0 + k;
            *(float4*)&s_row[w][k][f4] =
                (rr < Nrows) ? *(const float4*)&g_agg[(size_t)rr * NAB + f4] : z4;
        }
        __syncwarp();
        ull acc[4][2];
        #pragma unroll
        for (int k = 0; k < 4; k++) { acc[k][0] = b1p0; acc[k][1] = b1p1; }
        #pragma unroll 4
        for (int kk = 0; kk < NAB; kk++) {
            ulonglong2 wv = __ldg((const ulonglong2*)&W1[kk * NAB + f4]);
            #pragma unroll
            for (int k = 0; k < 4; k++) {
                float x = s_row[w][k][kk];          // uniform broadcast LDS
                ull hv = pk2(x, x);
                acc[k][0] = fma2(wv.x, hv, acc[k][0]);
                acc[k][1] = fma2(wv.y, hv, acc[k][1]);
            }
        }
        #pragma unroll
        for (int k = 0; k < 4; k++) {
            float2 v01 = up2(acc[k][0]);
            float2 v23 = up2(acc[k][1]);
            s_h[w][k][f4 + 0] = sspf(v01.x);
            s_h[w][k][f4 + 1] = sspf(v01.y);
            s_h[w][k][f4 + 2] = sspf(v23.x);
            s_h[w][k][f4 + 3] = sspf(v23.y);
        }
        __syncwarp();
        ull cc[4][2];
        #pragma unroll
        for (int k = 0; k < 4; k++) { cc[k][0] = b2p0; cc[k][1] = b2p1; }
        #pragma unroll 4
        for (int j = 0; j < NAB; j++) {
            ulonglong2 wv = __ldg((const ulonglong2*)&W2[j * NAB + f4]);
            #pragma unroll
            for (int k = 0; k < 4; k++) {
                float x = s_h[w][k][j];             // uniform broadcast LDS
                ull hv = pk2(x, x);
                cc[k][0] = fma2(wv.x, hv, cc[k][0]);
                cc[k][1] = fma2(wv.y, hv, cc[k][1]);
            }
        }
        #pragma unroll
        for (int k = 0; k < 4; k++) {
            int rr = r0 + k;
            if (rr < Nrows) {
                float2 v01 = up2(cc[k][0]);
                float2 v23 = up2(cc[k][1]);
                *(float4*)&out[(size_t)rr * NAB + f4] =
                    make_float4(v01.x, v01.y, v23.x, v23.y);
            }
        }
        __syncwarp();
    }
}

// ---------------------------------------------------------------------------
extern "C" void kernel_launch(void* const* d_in, const int* in_sizes, int n_in,
                              void* d_out, int out_size) {
    const float* r     = (const float*)d_in[0];
    const float* e     = (const float*)d_in[1];
    const int*   a     = (const int*)d_in[2];
    const float* W_df1 = (const float*)d_in[3];
    const float* b_df1 = (const float*)d_in[4];
    const float* W_df2 = (const float*)d_in[5];
    const float* b_df2 = (const float*)d_in[6];
    const float* W_af  = (const float*)d_in[7];
    const float* W_d1  = (const float*)d_in[8];
    const float* b_d1  = (const float*)d_in[9];
    const float* W_d2  = (const float*)d_in[10];
    const float* b_d2  = (const float*)d_in[11];
    float* out = (float*)d_out;

    int N = in_sizes[0] / NAB;
    int E = in_sizes[1];

    int nquads  = (N + 3) >> 2;
    int grid_rc = (nquads + 3) / 4;

    // 4 kernel launches/iter; profiled launch (L==3 mod 4) -> k_out
    k_table<<<TBN + 1, 128>>>(W_df1, b_df1, W_df2, b_df2);       // 0
    k_rf<<<grid_rc, 128>>>(r, W_af, N);                          // 1
    int nwork  = (E + 31) / 32;
    int grid_e = nwork < 2368 ? nwork : 2368;
    k_edge2<<<grid_e, 256>>>(e, a, E);                           // 2
    k_out<<<grid_rc, 128>>>(W_d1, b_d1, W_d2, b_d2, out, N);     // 3
}